// round 14
// baseline (speedup 1.0000x reference)
#include <cuda_runtime.h>
#include <cuda_fp16.h>
#include <cstdint>

typedef unsigned int u32;

#define NT 256
// smem byte offsets
#define O_SC   0
#define O_A1   5376          // 64 x 784 B fp16
#define O_A2   5376          // overlays A1 after fc1 (64 x 528 B); logits later
#define O_W    55552         // 2 x 20480 W double buffer
#define O_F2   55552         // F2 overlays W buffer 0 after fc2
#define SMB    96512
// const float indices
#define SW1 0
#define SB1 45
#define SW2 50
#define SB2 200
#define SFB1 210
#define SFB2 466
#define SPW 530
#define SPB 1298

__device__ __align__(16) __half g_w1p[12 * 256 * 40];
__device__ __align__(16) __half g_w2p[8 * 64 * 40];

__device__ __forceinline__ u32 smem_u32(const void* p) {
    u32 a; asm("{ .reg .u64 t; cvta.to.shared.u64 t, %1; cvt.u32.u64 %0, t; }" : "=r"(a) : "l"(p)); return a;
}
__device__ __forceinline__ void ldm4(u32 a, u32* d) {
    asm volatile("ldmatrix.sync.aligned.m8n8.x4.shared.b16 {%0,%1,%2,%3},[%4];"
                 : "=r"(d[0]), "=r"(d[1]), "=r"(d[2]), "=r"(d[3]) : "r"(a));
}
__device__ __forceinline__ void mma_f16(float* d, const u32* a, u32 b0, u32 b1) {
    asm volatile("mma.sync.aligned.m16n8k16.row.col.f32.f16.f16.f32 "
                 "{%0,%1,%2,%3},{%4,%5,%6,%7},{%8,%9},{%0,%1,%2,%3};"
                 : "+f"(d[0]), "+f"(d[1]), "+f"(d[2]), "+f"(d[3])
                 : "r"(a[0]), "r"(a[1]), "r"(a[2]), "r"(a[3]), "r"(b0), "r"(b1));
}
__device__ __forceinline__ u32 pack2h(float a, float b) {
    return ((u32)__half_as_ushort(__float2half_rn(b)) << 16)
         | (u32)__half_as_ushort(__float2half_rn(a));
}
__device__ __forceinline__ float sqrt_fast(float x) {
    float r; asm("sqrt.approx.f32 %0,%1;" : "=f"(r) : "f"(x)); return r;
}
__device__ __forceinline__ void cp16(u32 dst, const void* src) {
    asm volatile("cp.async.ca.shared.global [%0],[%1],16;" :: "r"(dst), "l"(src));
}
#define CP_COMMIT() asm volatile("cp.async.commit_group;" ::: "memory")
#define CP_WAIT0()  asm volatile("cp.async.wait_group 0;" ::: "memory")

__global__ void prep_kernel(const float* __restrict__ fw1, const float* __restrict__ fw2) {
    int i = blockIdx.x * 256 + threadIdx.x;
    if (i < 12 * 256 * 40) {
        int ch = i / 10240, rem = i % 10240, n = rem / 40, pos = rem % 40;
        int k = ch * 32 + pos;
        float v = (pos < 32 && k < 360) ? fw1[n * 360 + k] : 0.0f;
        g_w1p[i] = __float2half_rn(v);
    }
    if (i < 8 * 64 * 40) {
        int ch = i / 2560, rem = i % 2560, n = rem / 40, pos = rem % 40;
        int k = ch * 32 + pos;
        g_w2p[i] = __float2half_rn((pos < 32) ? fw2[n * 256 + k] : 0.0f);
    }
}

__global__ __launch_bounds__(NT, 2)
void convnet_mma_kernel(const float* __restrict__ sig,
                        const float* __restrict__ w1, const float* __restrict__ b1,
                        const float* __restrict__ w2, const float* __restrict__ b2,
                        const float* __restrict__ fb1, const float* __restrict__ fb2,
                        const float* __restrict__ pw, const float* __restrict__ pb,
                        float* __restrict__ out)
{
    extern __shared__ char smem[];
    const int tid = threadIdx.x, lane = tid & 31, wid = tid >> 5, bx = blockIdx.x;
    const int g = lane >> 2, q = lane & 3;
    const int warpm = wid & 3, warpn = wid >> 2;
    const int lrow = lane & 7, lsel = lane >> 3;
    const u32 sb = smem_u32(smem);
    float* SC = (float*)(smem + O_SC);

    for (int i = tid; i < 45; i += NT)  SC[SW1 + i] = w1[i];
    if (tid < 5)  SC[SB1 + tid] = b1[tid];
    for (int i = tid; i < 150; i += NT) SC[SW2 + i] = w2[i];
    if (tid < 10) SC[SB2 + tid] = b2[tid];
    SC[SFB1 + tid] = fb1[tid];
    if (tid < 64) SC[SFB2 + tid] = fb2[tid];
    for (int i = tid; i < 768; i += NT) SC[SPW + i] = pw[i];
    if (tid < 12) SC[SPB + tid] = pb[tid];
    {
        const float4* gsig = (const float4*)(sig + (size_t)bx * 64 * 150);
        float4* s4 = (float4*)(smem + O_W);
        for (int i = tid; i < 64 * 150 / 4; i += NT) s4[i] = gsig[i];
    }
    __syncthreads();

    // ---- featurize -> A1 fp16 [64][392] (parallel resummation std, R12) ----
    {
        const int s = tid & 63, t0 = (tid >> 6) * 9;
        const float* xs = (const float*)(smem + O_W) + s * 150;
        float sd[3][13];
#pragma unroll
        for (int c = 0; c < 3; ++c) {
            float xr[22];
#pragma unroll
            for (int j = 0; j < 22; ++j) xr[j] = xs[(t0 + j) * 3 + c];
#pragma unroll
            for (int tt = 0; tt < 13; ++tt) {
                float s1 = 0.f, s2 = 0.f;
#pragma unroll
                for (int j = 0; j < 10; ++j) { float v = xr[tt + j]; s1 += v; s2 += v * v; }
                sd[c][tt] = sqrt_fast(fmaxf((s2 - s1 * s1 * 0.1f) * (1.0f / 9.0f), 0.f));
            }
        }
        float h1[5][11];
#pragma unroll
        for (int o = 0; o < 5; ++o) {
            float bb = SC[SB1 + o];
#pragma unroll
            for (int tt = 0; tt < 11; ++tt) h1[o][tt] = bb;
#pragma unroll
            for (int c = 0; c < 3; ++c)
#pragma unroll
                for (int k = 0; k < 3; ++k) {
                    float w = SC[SW1 + o * 9 + c * 3 + k];
#pragma unroll
                    for (int tt = 0; tt < 11; ++tt) h1[o][tt] += w * sd[c][tt + k];
                }
#pragma unroll
            for (int tt = 0; tt < 11; ++tt) h1[o][tt] = fmaxf(h1[o][tt], 0.f);
        }
        __half* A1 = (__half*)(smem + O_A1);
#pragma unroll
        for (int o = 0; o < 10; ++o) {
            float a2[9];
            float bb = SC[SB2 + o];
#pragma unroll
            for (int tt = 0; tt < 9; ++tt) a2[tt] = bb;
#pragma unroll
            for (int i = 0; i < 5; ++i)
#pragma unroll
                for (int k = 0; k < 3; ++k) {
                    float w = SC[SW2 + o * 15 + i * 3 + k];
#pragma unroll
                    for (int tt = 0; tt < 9; ++tt) a2[tt] += w * h1[i][tt + k];
                }
#pragma unroll
            for (int tt = 0; tt < 9; ++tt)
                A1[s * 392 + (t0 + tt) * 10 + o] = __float2half_rn(fmaxf(a2[tt], 0.f));
        }
    }
    for (int i = tid; i < 64 * 24; i += NT) {
        int s = i / 24, k = 360 + i % 24;
        ((__half*)(smem + O_A1))[s * 392 + k] = __ushort_as_half((unsigned short)0);
    }

    // stage fc1 W chunk 0
    {
        const char* src = (const char*)g_w1p;
#pragma unroll
        for (int j = 0; j < 5; ++j) {
            int idx = tid + j * 256;
            cp16(sb + O_W + idx * 16, src + idx * 16);
        }
        CP_COMMIT();
    }
    CP_WAIT0();
    __syncthreads();

    // ---- fc1: 64x256, K=384, fp16 ----
    float acc[64];
#pragma unroll
    for (int i = 0; i < 64; ++i) acc[i] = 0.f;

    const u32 a1B = sb + O_A1
        + (u32)((warpm * 16 + lrow + (lsel & 1) * 8) * 784 + ((lsel >> 1) & 1) * 16);
    const u32 b1B = (u32)((warpn * 128 + lrow + ((lsel >> 1) & 1) * 8) * 80 + (lsel & 1) * 16);

#pragma unroll 1
    for (int ch = 0; ch < 12; ++ch) {
        if (ch < 11) {
            const char* src = (const char*)g_w1p + (ch + 1) * 20480;
            u32 dst = sb + O_W + (u32)((ch + 1) & 1) * 20480;
#pragma unroll
            for (int j = 0; j < 5; ++j) {
                int idx = tid + j * 256;
                cp16(dst + idx * 16, src + idx * 16);
            }
            CP_COMMIT();
        }
        const u32 bb = sb + O_W + (u32)(ch & 1) * 20480 + b1B;
        const u32 kof = (u32)(ch * 64);
#pragma unroll
        for (int ks = 0; ks < 2; ++ks) {
            u32 ah[4];
            ldm4(a1B + kof + ks * 32, ah);
            u32 bf[4][4];
#pragma unroll
            for (int pr = 0; pr < 4; ++pr) ldm4(bb + pr * 1280 + ks * 32, bf[pr]);
#pragma unroll
            for (int pr = 0; pr < 4; ++pr) {
                mma_f16(acc + pr * 8,     ah, bf[pr][0], bf[pr][1]);
                mma_f16(acc + pr * 8 + 4, ah, bf[pr][2], bf[pr][3]);
            }
#pragma unroll
            for (int pr = 0; pr < 4; ++pr) ldm4(bb + (pr + 4) * 1280 + ks * 32, bf[pr]);
#pragma unroll
            for (int pr = 0; pr < 4; ++pr) {
                mma_f16(acc + (pr + 4) * 8,     ah, bf[pr][0], bf[pr][1]);
                mma_f16(acc + (pr + 4) * 8 + 4, ah, bf[pr][2], bf[pr][3]);
            }
        }
        if (ch < 11) {
            CP_WAIT0();
            __syncthreads();
        }
    }

    // issue fc2 chunk-0 staging NOW (buf 0 free: last read was chunk 10),
    // so the copy overlaps the fc1 epilogue below.
    {
        const char* src = (const char*)g_w2p;
        int idx = tid;
        cp16(sb + O_W + idx * 16, src + idx * 16);
        if (tid < 64) {
            idx = 256 + tid;
            cp16(sb + O_W + idx * 16, src + idx * 16);
        }
        CP_COMMIT();
    }
    __syncthreads();   // all warps done reading A1 before A2 overwrites it

    // ---- fc1 epilogue -> A2 fp16 [64][264] ----
    {
        const int r0 = warpm * 16 + g;
#pragma unroll
        for (int nt = 0; nt < 16; ++nt) {
            const int n0 = warpn * 128 + nt * 8 + q * 2;
            float bb0 = SC[SFB1 + n0], bb1 = SC[SFB1 + n0 + 1];
            float v0 = fmaxf(acc[nt * 4 + 0] + bb0, 0.f), v1 = fmaxf(acc[nt * 4 + 1] + bb1, 0.f);
            float v2 = fmaxf(acc[nt * 4 + 2] + bb0, 0.f), v3 = fmaxf(acc[nt * 4 + 3] + bb1, 0.f);
            *(u32*)(smem + O_A2 + r0 * 528 + n0 * 2)       = pack2h(v0, v1);
            *(u32*)(smem + O_A2 + (r0 + 8) * 528 + n0 * 2) = pack2h(v2, v3);
        }
    }
    CP_WAIT0();
    __syncthreads();

    // ---- fc2: 64x64, K=256, fp16 ----
#pragma unroll
    for (int i = 0; i < 16; ++i) acc[i] = 0.f;
    const u32 a2B = sb + O_A2
        + (u32)((warpm * 16 + lrow + (lsel & 1) * 8) * 528 + ((lsel >> 1) & 1) * 16);
    const u32 b2B = (u32)((warpn * 32 + lrow + ((lsel >> 1) & 1) * 8) * 80 + (lsel & 1) * 16);

#pragma unroll 1
    for (int ch = 0; ch < 8; ++ch) {
        if (ch < 7) {
            const char* src = (const char*)g_w2p + (ch + 1) * 5120;
            u32 dst = sb + O_W + (u32)((ch + 1) & 1) * 20480;
            int idx = tid;
            cp16(dst + idx * 16, src + idx * 16);
            if (tid < 64) {
                idx = 256 + tid;
                cp16(dst + idx * 16, src + idx * 16);
            }
            CP_COMMIT();
        }
        const u32 bb = sb + O_W + (u32)(ch & 1) * 20480 + b2B;
        const u32 kof = (u32)(ch * 64);
#pragma unroll
        for (int ks = 0; ks < 2; ++ks) {
            u32 ah[4];
            ldm4(a2B + kof + ks * 32, ah);
            u32 bf[2][4];
#pragma unroll
            for (int pr = 0; pr < 2; ++pr) ldm4(bb + pr * 1280 + ks * 32, bf[pr]);
#pragma unroll
            for (int pr = 0; pr < 2; ++pr) {
                mma_f16(acc + pr * 8,     ah, bf[pr][0], bf[pr][1]);
                mma_f16(acc + pr * 8 + 4, ah, bf[pr][2], bf[pr][3]);
            }
        }
        if (ch < 7) {
            CP_WAIT0();
            __syncthreads();
        }
    }
    __syncthreads();

    // ---- fc2 epilogue -> F2 [64][69] f32 ----
    {
        float* f2 = (float*)(smem + O_F2);
        const int r0 = warpm * 16 + g;
#pragma unroll
        for (int nt = 0; nt < 4; ++nt) {
            const int n0 = warpn * 32 + nt * 8 + q * 2;
            float bb0 = SC[SFB2 + n0], bb1 = SC[SFB2 + n0 + 1];
            f2[r0 * 69 + n0]           = fmaxf(acc[nt * 4 + 0] + bb0, 0.f);
            f2[r0 * 69 + n0 + 1]       = fmaxf(acc[nt * 4 + 1] + bb1, 0.f);
            f2[(r0 + 8) * 69 + n0]     = fmaxf(acc[nt * 4 + 2] + bb0, 0.f);
            f2[(r0 + 8) * 69 + n0 + 1] = fmaxf(acc[nt * 4 + 3] + bb1, 0.f);
        }
    }
    __syncthreads();

    // ---- head stage 1: all 256 threads, 3 logits each ----
    {
        float* lg = (float*)(smem + O_A2);   // A2 dead; logits [64][13]
        const int s = tid >> 2, jg = (tid & 3) * 3;
        const float* f2 = (const float*)(smem + O_F2) + s * 69;
        const float* pw0 = SC + SPW + jg * 64;
        float l0 = SC[SPB + jg], l1 = SC[SPB + jg + 1], l2 = SC[SPB + jg + 2];
#pragma unroll 8
        for (int k = 0; k < 64; ++k) {
            float v = f2[k];
            l0 += v * pw0[k];
            l1 += v * pw0[64 + k];
            l2 += v * pw0[128 + k];
        }
        lg[s * 13 + jg]     = l0;
        lg[s * 13 + jg + 1] = l1;
        lg[s * 13 + jg + 2] = l2;
    }
    __syncthreads();

    // ---- head stage 2: 64 threads, log_softmax + store ----
    if (tid < 64) {
        const float* lg = (const float*)(smem + O_A2) + tid * 13;
        float l[12];
#pragma unroll
        for (int j = 0; j < 12; ++j) l[j] = lg[j];
        float m = l[0];
#pragma unroll
        for (int j = 1; j < 12; ++j) m = fmaxf(m, l[j]);
        float ssum = 0.f;
#pragma unroll
        for (int j = 0; j < 12; ++j) ssum += __expf(l[j] - m);
        float lse = m + __logf(ssum);
        float* op = out + ((size_t)bx * 64 + tid) * 12;
#pragma unroll
        for (int j = 0; j < 12; ++j) op[j] = l[j] - lse;
    }
}

extern "C" void kernel_launch(void* const* d_in, const int* in_sizes, int n_in,
                              void* d_out, int out_size)
{
    (void)n_in; (void)out_size;
    const float* sig = (const float*)d_in[0];
    const float* w1  = (const float*)d_in[1];
    const float* b1  = (const float*)d_in[2];
    const float* w2  = (const float*)d_in[3];
    const float* b2  = (const float*)d_in[4];
    const float* fw1 = (const float*)d_in[5];
    const float* fb1 = (const float*)d_in[6];
    const float* fw2 = (const float*)d_in[7];
    const float* fb2 = (const float*)d_in[8];
    const float* pw  = (const float*)d_in[9];
    const float* pb  = (const float*)d_in[10];
    float* out = (float*)d_out;

    const int B = in_sizes[0] / 150;
    prep_kernel<<<480, 256>>>(fw1, fw2);
    cudaFuncSetAttribute(convnet_mma_kernel, cudaFuncAttributeMaxDynamicSharedMemorySize, SMB);
    convnet_mma_kernel<<<B / 64, NT, SMB>>>(sig, w1, b1, w2, b2, fb1, fb2, pw, pb, out);
}

// round 15
// speedup vs baseline: 1.2193x; 1.2193x over previous
#include <cuda_runtime.h>
#include <cuda_fp16.h>
#include <cstdint>

typedef unsigned int u32;

#define NT 256
// smem byte offsets
#define O_SC   0
#define O_A1   5376          // 64 x 784 B fp16
#define O_A2   5376          // overlays A1 after fc1 (64 x 528 B)
#define O_W    55552         // 2 x 20480 W double buffer; signal tile + w2 table early
#define O_TBL  (55552 + 38400) // packed conv2 weights (75 u32) behind signal
#define O_F2   55552         // F2 overlays W buffer 0 after fc2
#define SMB    96512
// const float indices
#define SW1 0
#define SB1 45
#define SW2 50
#define SB2 200
#define SFB1 210
#define SFB2 466
#define SPW 530
#define SPB 1298

__device__ __align__(16) __half g_w1p[12 * 256 * 40];
__device__ __align__(16) __half g_w2p[8 * 64 * 40];

__device__ __forceinline__ u32 smem_u32(const void* p) {
    u32 a; asm("{ .reg .u64 t; cvta.to.shared.u64 t, %1; cvt.u32.u64 %0, t; }" : "=r"(a) : "l"(p)); return a;
}
__device__ __forceinline__ void ldm4(u32 a, u32* d) {
    asm volatile("ldmatrix.sync.aligned.m8n8.x4.shared.b16 {%0,%1,%2,%3},[%4];"
                 : "=r"(d[0]), "=r"(d[1]), "=r"(d[2]), "=r"(d[3]) : "r"(a));
}
__device__ __forceinline__ void mma_f16(float* d, const u32* a, u32 b0, u32 b1) {
    asm volatile("mma.sync.aligned.m16n8k16.row.col.f32.f16.f16.f32 "
                 "{%0,%1,%2,%3},{%4,%5,%6,%7},{%8,%9},{%0,%1,%2,%3};"
                 : "+f"(d[0]), "+f"(d[1]), "+f"(d[2]), "+f"(d[3])
                 : "r"(a[0]), "r"(a[1]), "r"(a[2]), "r"(a[3]), "r"(b0), "r"(b1));
}
__device__ __forceinline__ u32 pack2h(float a, float b) {
    return ((u32)__half_as_ushort(__float2half_rn(b)) << 16)
         | (u32)__half_as_ushort(__float2half_rn(a));
}
__device__ __forceinline__ float sqrt_fast(float x) {
    float r; asm("sqrt.approx.f32 %0,%1;" : "=f"(r) : "f"(x)); return r;
}
__device__ __forceinline__ void cp16(u32 dst, const void* src) {
    asm volatile("cp.async.ca.shared.global [%0],[%1],16;" :: "r"(dst), "l"(src));
}
#define CP_COMMIT() asm volatile("cp.async.commit_group;" ::: "memory")
#define CP_WAIT0()  asm volatile("cp.async.wait_group 0;" ::: "memory")

__global__ void prep_kernel(const float* __restrict__ fw1, const float* __restrict__ fw2) {
    int i = blockIdx.x * 256 + threadIdx.x;
    if (i < 12 * 256 * 40) {
        int ch = i / 10240, rem = i % 10240, n = rem / 40, pos = rem % 40;
        int k = ch * 32 + pos;
        float v = (pos < 32 && k < 360) ? fw1[n * 360 + k] : 0.0f;
        g_w1p[i] = __float2half_rn(v);
    }
    if (i < 8 * 64 * 40) {
        int ch = i / 2560, rem = i % 2560, n = rem / 40, pos = rem % 40;
        int k = ch * 32 + pos;
        g_w2p[i] = __float2half_rn((pos < 32) ? fw2[n * 256 + k] : 0.0f);
    }
}

__global__ __launch_bounds__(NT, 2)
void convnet_mma_kernel(const float* __restrict__ sig,
                        const float* __restrict__ w1, const float* __restrict__ b1,
                        const float* __restrict__ w2, const float* __restrict__ b2,
                        const float* __restrict__ fb1, const float* __restrict__ fb2,
                        const float* __restrict__ pw, const float* __restrict__ pb,
                        float* __restrict__ out)
{
    extern __shared__ char smem[];
    const int tid = threadIdx.x, lane = tid & 31, wid = tid >> 5, bx = blockIdx.x;
    const int g = lane >> 2, q = lane & 3;
    const int warpm = wid & 3, warpn = wid >> 2;
    const int lrow = lane & 7, lsel = lane >> 3;
    const u32 sb = smem_u32(smem);
    float* SC = (float*)(smem + O_SC);

    for (int i = tid; i < 45; i += NT)  SC[SW1 + i] = w1[i];
    if (tid < 5)  SC[SB1 + tid] = b1[tid];
    for (int i = tid; i < 150; i += NT) SC[SW2 + i] = w2[i];
    if (tid < 10) SC[SB2 + tid] = b2[tid];
    SC[SFB1 + tid] = fb1[tid];
    if (tid < 64) SC[SFB2 + tid] = fb2[tid];
    for (int i = tid; i < 768; i += NT) SC[SPW + i] = pw[i];
    if (tid < 12) SC[SPB + tid] = pb[tid];
    {
        const float4* gsig = (const float4*)(sig + (size_t)bx * 64 * 150);
        float4* s4 = (float4*)(smem + O_W);
        for (int i = tid; i < 64 * 150 / 4; i += NT) s4[i] = gsig[i];
    }
    __syncthreads();

    // build packed conv2 weight table (o-pairs): tbl[op*15 + i*3 + k]
    if (tid < 75) {
        int op = tid / 15, ik = tid % 15;
        ((u32*)(smem + O_TBL))[tid] =
            pack2h(SC[SW2 + (2 * op) * 15 + ik], SC[SW2 + (2 * op + 1) * 15 + ik]);
    }
    __syncthreads();

    // ---- featurize -> A1 fp16 [64][392] (tree sums + half2 conv2) ----
    {
        const int s = tid & 63, t0 = (tid >> 6) * 9;
        const float* xs = (const float*)(smem + O_W) + s * 150;
        const u32* tbl = (const u32*)(smem + O_TBL);
        float sd[3][13];
#pragma unroll
        for (int c = 0; c < 3; ++c) {
            float xr[22];
#pragma unroll
            for (int j = 0; j < 22; ++j) xr[j] = xs[(t0 + j) * 3 + c];
            {   // squared-sum windows via pair/quad tree
                float p2[21], q2[19];
#pragma unroll
                for (int j = 0; j < 21; ++j) p2[j] = fmaf(xr[j + 1], xr[j + 1], xr[j] * xr[j]);
#pragma unroll
                for (int j = 0; j < 19; ++j) q2[j] = p2[j] + p2[j + 2];
#pragma unroll
                for (int tt = 0; tt < 13; ++tt) sd[c][tt] = q2[tt] + q2[tt + 4] + p2[tt + 8];
            }
            {   // plain-sum windows, then variance + sqrt
                float p1[21], q1[19];
#pragma unroll
                for (int j = 0; j < 21; ++j) p1[j] = xr[j] + xr[j + 1];
#pragma unroll
                for (int j = 0; j < 19; ++j) q1[j] = p1[j] + p1[j + 2];
#pragma unroll
                for (int tt = 0; tt < 13; ++tt) {
                    float s1 = q1[tt] + q1[tt + 4] + p1[tt + 8];
                    sd[c][tt] = sqrt_fast(fmaxf((sd[c][tt] - s1 * s1 * 0.1f) * (1.0f / 9.0f), 0.f));
                }
            }
        }
        // conv1 row-by-row, conv2 accumulated in half2 output-pairs
        __half2 a2[5][9];
#pragma unroll
        for (int op = 0; op < 5; ++op) {
            __half2 b2h = __floats2half2_rn(SC[SB2 + 2 * op], SC[SB2 + 2 * op + 1]);
#pragma unroll
            for (int tt = 0; tt < 9; ++tt) a2[op][tt] = b2h;
        }
#pragma unroll
        for (int i = 0; i < 5; ++i) {
            float h1r[11];
            float bb = SC[SB1 + i];
#pragma unroll
            for (int tt = 0; tt < 11; ++tt) h1r[tt] = bb;
#pragma unroll
            for (int c = 0; c < 3; ++c)
#pragma unroll
                for (int k = 0; k < 3; ++k) {
                    float w = SC[SW1 + i * 9 + c * 3 + k];
#pragma unroll
                    for (int tt = 0; tt < 11; ++tt) h1r[tt] += w * sd[c][tt + k];
                }
#pragma unroll
            for (int tt = 0; tt < 11; ++tt) h1r[tt] = fmaxf(h1r[tt], 0.f);
            u32 w2r[15];
#pragma unroll
            for (int z = 0; z < 15; ++z) w2r[(z / 3) * 3 + (z % 3)] = tbl[(z / 3) * 15 + i * 3 + (z % 3)];
#pragma unroll
            for (int k = 0; k < 3; ++k)
#pragma unroll
                for (int tt = 0; tt < 9; ++tt) {
                    __half2 hb = __float2half2_rn(h1r[tt + k]);
#pragma unroll
                    for (int op = 0; op < 5; ++op)
                        a2[op][tt] = __hfma2(hb, *(const __half2*)&w2r[op * 3 + k], a2[op][tt]);
                }
        }
        {
            __half2 z2 = __float2half2_rn(0.f);
#pragma unroll
            for (int op = 0; op < 5; ++op)
#pragma unroll
                for (int tt = 0; tt < 9; ++tt) {
                    __half2 v = __hmax2(a2[op][tt], z2);
                    *(__half2*)(smem + O_A1 + (s * 392 + (t0 + tt) * 10 + 2 * op) * 2) = v;
                }
        }
    }
    for (int i = tid; i < 64 * 24; i += NT) {
        int s = i / 24, k = 360 + i % 24;
        ((__half*)(smem + O_A1))[s * 392 + k] = __ushort_as_half((unsigned short)0);
    }
    __syncthreads();   // signal region fully read before W staging overwrites it

    // stage fc1 W chunk 0
    {
        const char* src = (const char*)g_w1p;
#pragma unroll
        for (int j = 0; j < 5; ++j) {
            int idx = tid + j * 256;
            cp16(sb + O_W + idx * 16, src + idx * 16);
        }
        CP_COMMIT();
    }
    CP_WAIT0();
    __syncthreads();

    // ---- fc1: 64x256, K=384, fp16 ----
    float acc[64];
#pragma unroll
    for (int i = 0; i < 64; ++i) acc[i] = 0.f;

    const u32 a1B = sb + O_A1
        + (u32)((warpm * 16 + lrow + (lsel & 1) * 8) * 784 + ((lsel >> 1) & 1) * 16);
    const u32 b1B = (u32)((warpn * 128 + lrow + ((lsel >> 1) & 1) * 8) * 80 + (lsel & 1) * 16);

#pragma unroll 1
    for (int ch = 0; ch < 12; ++ch) {
        if (ch < 11) {
            const char* src = (const char*)g_w1p + (ch + 1) * 20480;
            u32 dst = sb + O_W + (u32)((ch + 1) & 1) * 20480;
#pragma unroll
            for (int j = 0; j < 5; ++j) {
                int idx = tid + j * 256;
                cp16(dst + idx * 16, src + idx * 16);
            }
            CP_COMMIT();
        }
        const u32 bb = sb + O_W + (u32)(ch & 1) * 20480 + b1B;
        const u32 kof = (u32)(ch * 64);
#pragma unroll
        for (int ks = 0; ks < 2; ++ks) {
            u32 ah[4];
            ldm4(a1B + kof + ks * 32, ah);
            u32 bf[4][4];
#pragma unroll
            for (int pr = 0; pr < 4; ++pr) ldm4(bb + pr * 1280 + ks * 32, bf[pr]);
#pragma unroll
            for (int pr = 0; pr < 4; ++pr) {
                mma_f16(acc + pr * 8,     ah, bf[pr][0], bf[pr][1]);
                mma_f16(acc + pr * 8 + 4, ah, bf[pr][2], bf[pr][3]);
            }
#pragma unroll
            for (int pr = 0; pr < 4; ++pr) ldm4(bb + (pr + 4) * 1280 + ks * 32, bf[pr]);
#pragma unroll
            for (int pr = 0; pr < 4; ++pr) {
                mma_f16(acc + (pr + 4) * 8,     ah, bf[pr][0], bf[pr][1]);
                mma_f16(acc + (pr + 4) * 8 + 4, ah, bf[pr][2], bf[pr][3]);
            }
        }
        if (ch < 11) {
            CP_WAIT0();
            __syncthreads();
        }
    }
    __syncthreads();

    // ---- fc1 epilogue -> A2 fp16 [64][264] ----
    {
        const int r0 = warpm * 16 + g;
#pragma unroll
        for (int nt = 0; nt < 16; ++nt) {
            const int n0 = warpn * 128 + nt * 8 + q * 2;
            float bb0 = SC[SFB1 + n0], bb1 = SC[SFB1 + n0 + 1];
            float v0 = fmaxf(acc[nt * 4 + 0] + bb0, 0.f), v1 = fmaxf(acc[nt * 4 + 1] + bb1, 0.f);
            float v2 = fmaxf(acc[nt * 4 + 2] + bb0, 0.f), v3 = fmaxf(acc[nt * 4 + 3] + bb1, 0.f);
            *(u32*)(smem + O_A2 + r0 * 528 + n0 * 2)       = pack2h(v0, v1);
            *(u32*)(smem + O_A2 + (r0 + 8) * 528 + n0 * 2) = pack2h(v2, v3);
        }
    }
    {
        const char* src = (const char*)g_w2p;
        int idx = tid;
        cp16(sb + O_W + idx * 16, src + idx * 16);
        if (tid < 64) {
            idx = 256 + tid;
            cp16(sb + O_W + idx * 16, src + idx * 16);
        }
        CP_COMMIT();
    }
    CP_WAIT0();
    __syncthreads();

    // ---- fc2: 64x64, K=256, fp16 ----
#pragma unroll
    for (int i = 0; i < 16; ++i) acc[i] = 0.f;
    const u32 a2B = sb + O_A2
        + (u32)((warpm * 16 + lrow + (lsel & 1) * 8) * 528 + ((lsel >> 1) & 1) * 16);
    const u32 b2B = (u32)((warpn * 32 + lrow + ((lsel >> 1) & 1) * 8) * 80 + (lsel & 1) * 16);

#pragma unroll 1
    for (int ch = 0; ch < 8; ++ch) {
        if (ch < 7) {
            const char* src = (const char*)g_w2p + (ch + 1) * 5120;
            u32 dst = sb + O_W + (u32)((ch + 1) & 1) * 20480;
            int idx = tid;
            cp16(dst + idx * 16, src + idx * 16);
            if (tid < 64) {
                idx = 256 + tid;
                cp16(dst + idx * 16, src + idx * 16);
            }
            CP_COMMIT();
        }
        const u32 bb = sb + O_W + (u32)(ch & 1) * 20480 + b2B;
        const u32 kof = (u32)(ch * 64);
#pragma unroll
        for (int ks = 0; ks < 2; ++ks) {
            u32 ah[4];
            ldm4(a2B + kof + ks * 32, ah);
            u32 bf[2][4];
#pragma unroll
            for (int pr = 0; pr < 2; ++pr) ldm4(bb + pr * 1280 + ks * 32, bf[pr]);
#pragma unroll
            for (int pr = 0; pr < 2; ++pr) {
                mma_f16(acc + pr * 8,     ah, bf[pr][0], bf[pr][1]);
                mma_f16(acc + pr * 8 + 4, ah, bf[pr][2], bf[pr][3]);
            }
        }
        if (ch < 7) {
            CP_WAIT0();
            __syncthreads();
        }
    }
    __syncthreads();

    // ---- fc2 epilogue -> F2 [64][69] f32 ----
    {
        float* f2 = (float*)(smem + O_F2);
        const int r0 = warpm * 16 + g;
#pragma unroll
        for (int nt = 0; nt < 4; ++nt) {
            const int n0 = warpn * 32 + nt * 8 + q * 2;
            float bb0 = SC[SFB2 + n0], bb1 = SC[SFB2 + n0 + 1];
            f2[r0 * 69 + n0]           = fmaxf(acc[nt * 4 + 0] + bb0, 0.f);
            f2[r0 * 69 + n0 + 1]       = fmaxf(acc[nt * 4 + 1] + bb1, 0.f);
            f2[(r0 + 8) * 69 + n0]     = fmaxf(acc[nt * 4 + 2] + bb0, 0.f);
            f2[(r0 + 8) * 69 + n0 + 1] = fmaxf(acc[nt * 4 + 3] + bb1, 0.f);
        }
    }
    __syncthreads();

    // ---- head (64->12) + log_softmax (R12 structure) ----
    if (tid < 64) {
        const float* f2 = (const float*)(smem + O_F2) + tid * 69;
        float l[12];
#pragma unroll
        for (int j = 0; j < 12; ++j) l[j] = SC[SPB + j];
#pragma unroll 8
        for (int k = 0; k < 64; ++k) {
            float v = f2[k];
#pragma unroll
            for (int j = 0; j < 12; ++j) l[j] += v * SC[SPW + j * 64 + k];
        }
        float m = l[0];
#pragma unroll
        for (int j = 1; j < 12; ++j) m = fmaxf(m, l[j]);
        float ssum = 0.f;
#pragma unroll
        for (int j = 0; j < 12; ++j) ssum += __expf(l[j] - m);
        float lse = m + __logf(ssum);
        float* op = out + ((size_t)bx * 64 + tid) * 12;
#pragma unroll
        for (int j = 0; j < 12; ++j) op[j] = l[j] - lse;
    }
}

extern "C" void kernel_launch(void* const* d_in, const int* in_sizes, int n_in,
                              void* d_out, int out_size)
{
    (void)n_in; (void)out_size;
    const float* sig = (const float*)d_in[0];
    const float* w1  = (const float*)d_in[1];
    const float* b1  = (const float*)d_in[2];
    const float* w2  = (const float*)d_in[3];
    const float* b2  = (const float*)d_in[4];
    const float* fw1 = (const float*)d_in[5];
    const float* fb1 = (const float*)d_in[6];
    const float* fw2 = (const float*)d_in[7];
    const float* fb2 = (const float*)d_in[8];
    const float* pw  = (const float*)d_in[9];
    const float* pb  = (const float*)d_in[10];
    float* out = (float*)d_out;

    const int B = in_sizes[0] / 150;
    prep_kernel<<<480, 256>>>(fw1, fw2);
    cudaFuncSetAttribute(convnet_mma_kernel, cudaFuncAttributeMaxDynamicSharedMemorySize, SMB);
    convnet_mma_kernel<<<B / 64, NT, SMB>>>(sig, w1, b1, w2, b2, fb1, fb2, pw, pb, out);
}

// round 16
// speedup vs baseline: 1.2277x; 1.0069x over previous
#include <cuda_runtime.h>
#include <cuda_fp16.h>
#include <cstdint>

typedef unsigned int u32;

#define NT 256
// smem byte offsets
#define O_SC   0
#define O_A1   5376          // 64 x 784 B fp16
#define O_A2   5376          // overlays A1 after fc1 (64 x 528 B)
#define O_W    55552         // 2 x 20480 W double buffer; signal tile + w2 table early
#define O_TBL  (55552 + 38400) // packed conv2 weights (75 u32) behind signal
#define O_F2   55552         // F2 overlays W buffer 0 after fc2
#define SMB    96512
// const float indices
#define SW1 0
#define SB1 45
#define SW2 50
#define SB2 200
#define SFB1 210
#define SFB2 466
#define SPW 530
#define SPB 1298

__device__ __align__(16) __half g_w1p[12 * 256 * 40];
__device__ __align__(16) __half g_w2p[8 * 64 * 40];

__device__ __forceinline__ u32 smem_u32(const void* p) {
    u32 a; asm("{ .reg .u64 t; cvta.to.shared.u64 t, %1; cvt.u32.u64 %0, t; }" : "=r"(a) : "l"(p)); return a;
}
__device__ __forceinline__ void ldm4(u32 a, u32* d) {
    asm volatile("ldmatrix.sync.aligned.m8n8.x4.shared.b16 {%0,%1,%2,%3},[%4];"
                 : "=r"(d[0]), "=r"(d[1]), "=r"(d[2]), "=r"(d[3]) : "r"(a));
}
__device__ __forceinline__ void mma_f16(float* d, const u32* a, u32 b0, u32 b1) {
    asm volatile("mma.sync.aligned.m16n8k16.row.col.f32.f16.f16.f32 "
                 "{%0,%1,%2,%3},{%4,%5,%6,%7},{%8,%9},{%0,%1,%2,%3};"
                 : "+f"(d[0]), "+f"(d[1]), "+f"(d[2]), "+f"(d[3])
                 : "r"(a[0]), "r"(a[1]), "r"(a[2]), "r"(a[3]), "r"(b0), "r"(b1));
}
__device__ __forceinline__ u32 pack2h(float a, float b) {
    return ((u32)__half_as_ushort(__float2half_rn(b)) << 16)
         | (u32)__half_as_ushort(__float2half_rn(a));
}
__device__ __forceinline__ float sqrt_fast(float x) {
    float r; asm("sqrt.approx.f32 %0,%1;" : "=f"(r) : "f"(x)); return r;
}
__device__ __forceinline__ void cp16(u32 dst, const void* src) {
    asm volatile("cp.async.ca.shared.global [%0],[%1],16;" :: "r"(dst), "l"(src));
}
#define CP_COMMIT() asm volatile("cp.async.commit_group;" ::: "memory")
#define CP_WAIT0()  asm volatile("cp.async.wait_group 0;" ::: "memory")

__global__ void prep_kernel(const float* __restrict__ fw1, const float* __restrict__ fw2) {
    int i = blockIdx.x * 256 + threadIdx.x;
    if (i < 12 * 256 * 40) {
        int ch = i / 10240, rem = i % 10240, n = rem / 40, pos = rem % 40;
        int k = ch * 32 + pos;
        float v = (pos < 32 && k < 360) ? fw1[n * 360 + k] : 0.0f;
        g_w1p[i] = __float2half_rn(v);
    }
    if (i < 8 * 64 * 40) {
        int ch = i / 2560, rem = i % 2560, n = rem / 40, pos = rem % 40;
        int k = ch * 32 + pos;
        g_w2p[i] = __float2half_rn((pos < 32) ? fw2[n * 256 + k] : 0.0f);
    }
}

__global__ __launch_bounds__(NT, 2)
void convnet_mma_kernel(const float* __restrict__ sig,
                        const float* __restrict__ w1, const float* __restrict__ b1,
                        const float* __restrict__ w2, const float* __restrict__ b2,
                        const float* __restrict__ fb1, const float* __restrict__ fb2,
                        const float* __restrict__ pw, const float* __restrict__ pb,
                        float* __restrict__ out)
{
    extern __shared__ char smem[];
    const int tid = threadIdx.x, lane = tid & 31, wid = tid >> 5, bx = blockIdx.x;
    const int g = lane >> 2, q = lane & 3;
    const int warpm = wid & 3, warpn = wid >> 2;
    const int lrow = lane & 7, lsel = lane >> 3;
    const u32 sb = smem_u32(smem);
    float* SC = (float*)(smem + O_SC);

    for (int i = tid; i < 45; i += NT)  SC[SW1 + i] = w1[i];
    if (tid < 5)  SC[SB1 + tid] = b1[tid];
    for (int i = tid; i < 150; i += NT) SC[SW2 + i] = w2[i];
    if (tid < 10) SC[SB2 + tid] = b2[tid];
    SC[SFB1 + tid] = fb1[tid];
    if (tid < 64) SC[SFB2 + tid] = fb2[tid];
    for (int i = tid; i < 768; i += NT) SC[SPW + i] = pw[i];
    if (tid < 12) SC[SPB + tid] = pb[tid];
    {
        const float4* gsig = (const float4*)(sig + (size_t)bx * 64 * 150);
        float4* s4 = (float4*)(smem + O_W);
        for (int i = tid; i < 64 * 150 / 4; i += NT) s4[i] = gsig[i];
    }
    __syncthreads();

    // build packed conv2 weight table (o-pairs): tbl[op*15 + i*3 + k]
    if (tid < 75) {
        int op = tid / 15, ik = tid % 15;
        ((u32*)(smem + O_TBL))[tid] =
            pack2h(SC[SW2 + (2 * op) * 15 + ik], SC[SW2 + (2 * op + 1) * 15 + ik]);
    }
    __syncthreads();

    // ---- featurize -> A1 fp16 [64][392] ----
    {
        const int s = tid & 63, t0 = (tid >> 6) * 9;
        const float* xs = (const float*)(smem + O_W) + s * 150;
        const u32* tbl = (const u32*)(smem + O_TBL);
        float sd[3][13];
        // channels 0,1 packed in half2 (independent trees -> SIMD)
        {
            __half2 xh[22];
#pragma unroll
            for (int j = 0; j < 22; ++j)
                xh[j] = __floats2half2_rn(xs[(t0 + j) * 3], xs[(t0 + j) * 3 + 1]);
            __half2 p2[21], p1[21];
#pragma unroll
            for (int j = 0; j < 21; ++j) {
                p2[j] = __hfma2(xh[j + 1], xh[j + 1], __hmul2(xh[j], xh[j]));
                p1[j] = __hadd2(xh[j], xh[j + 1]);
            }
            __half2 q2[19], q1[19];
#pragma unroll
            for (int j = 0; j < 19; ++j) {
                q2[j] = __hadd2(p2[j], p2[j + 2]);
                q1[j] = __hadd2(p1[j], p1[j + 2]);
            }
#pragma unroll
            for (int tt = 0; tt < 13; ++tt) {
                float2 s2f = __half22float2(__hadd2(__hadd2(q2[tt], q2[tt + 4]), p2[tt + 8]));
                float2 s1f = __half22float2(__hadd2(__hadd2(q1[tt], q1[tt + 4]), p1[tt + 8]));
                sd[0][tt] = sqrt_fast(fmaxf((s2f.x - s1f.x * s1f.x * 0.1f) * (1.0f / 9.0f), 0.f));
                sd[1][tt] = sqrt_fast(fmaxf((s2f.y - s1f.y * s1f.y * 0.1f) * (1.0f / 9.0f), 0.f));
            }
        }
        // channel 2 scalar f32 (R15 tree)
        {
            float xr[22];
#pragma unroll
            for (int j = 0; j < 22; ++j) xr[j] = xs[(t0 + j) * 3 + 2];
            float p2[21], q2[19];
#pragma unroll
            for (int j = 0; j < 21; ++j) p2[j] = fmaf(xr[j + 1], xr[j + 1], xr[j] * xr[j]);
#pragma unroll
            for (int j = 0; j < 19; ++j) q2[j] = p2[j] + p2[j + 2];
            float w2s_[13];
#pragma unroll
            for (int tt = 0; tt < 13; ++tt) w2s_[tt] = q2[tt] + q2[tt + 4] + p2[tt + 8];
            float p1[21], q1[19];
#pragma unroll
            for (int j = 0; j < 21; ++j) p1[j] = xr[j] + xr[j + 1];
#pragma unroll
            for (int j = 0; j < 19; ++j) q1[j] = p1[j] + p1[j + 2];
#pragma unroll
            for (int tt = 0; tt < 13; ++tt) {
                float s1 = q1[tt] + q1[tt + 4] + p1[tt + 8];
                sd[2][tt] = sqrt_fast(fmaxf((w2s_[tt] - s1 * s1 * 0.1f) * (1.0f / 9.0f), 0.f));
            }
        }
        // conv1 row-by-row (f32), conv2 accumulated in half2 output-pairs
        __half2 a2[5][9];
#pragma unroll
        for (int op = 0; op < 5; ++op) {
            __half2 b2h = __floats2half2_rn(SC[SB2 + 2 * op], SC[SB2 + 2 * op + 1]);
#pragma unroll
            for (int tt = 0; tt < 9; ++tt) a2[op][tt] = b2h;
        }
#pragma unroll
        for (int i = 0; i < 5; ++i) {
            float h1r[11];
            float bb = SC[SB1 + i];
#pragma unroll
            for (int tt = 0; tt < 11; ++tt) h1r[tt] = bb;
#pragma unroll
            for (int c = 0; c < 3; ++c)
#pragma unroll
                for (int k = 0; k < 3; ++k) {
                    float w = SC[SW1 + i * 9 + c * 3 + k];
#pragma unroll
                    for (int tt = 0; tt < 11; ++tt) h1r[tt] += w * sd[c][tt + k];
                }
#pragma unroll
            for (int tt = 0; tt < 11; ++tt) h1r[tt] = fmaxf(h1r[tt], 0.f);
            u32 w2r[15];
#pragma unroll
            for (int z = 0; z < 15; ++z) w2r[(z / 3) * 3 + (z % 3)] = tbl[(z / 3) * 15 + i * 3 + (z % 3)];
#pragma unroll
            for (int k = 0; k < 3; ++k)
#pragma unroll
                for (int tt = 0; tt < 9; ++tt) {
                    __half2 hb = __float2half2_rn(h1r[tt + k]);
#pragma unroll
                    for (int op = 0; op < 5; ++op)
                        a2[op][tt] = __hfma2(hb, *(const __half2*)&w2r[op * 3 + k], a2[op][tt]);
                }
        }
        {
            __half2 z2 = __float2half2_rn(0.f);
#pragma unroll
            for (int op = 0; op < 5; ++op)
#pragma unroll
                for (int tt = 0; tt < 9; ++tt) {
                    __half2 v = __hmax2(a2[op][tt], z2);
                    *(__half2*)(smem + O_A1 + (s * 392 + (t0 + tt) * 10 + 2 * op) * 2) = v;
                }
        }
    }
    for (int i = tid; i < 64 * 24; i += NT) {
        int s = i / 24, k = 360 + i % 24;
        ((__half*)(smem + O_A1))[s * 392 + k] = __ushort_as_half((unsigned short)0);
    }
    __syncthreads();   // signal region fully read before W staging overwrites it

    // stage fc1 W chunk 0
    {
        const char* src = (const char*)g_w1p;
#pragma unroll
        for (int j = 0; j < 5; ++j) {
            int idx = tid + j * 256;
            cp16(sb + O_W + idx * 16, src + idx * 16);
        }
        CP_COMMIT();
    }
    CP_WAIT0();
    __syncthreads();

    // ---- fc1: 64x256, K=384, fp16 ----
    float acc[64];
#pragma unroll
    for (int i = 0; i < 64; ++i) acc[i] = 0.f;

    const u32 a1B = sb + O_A1
        + (u32)((warpm * 16 + lrow + (lsel & 1) * 8) * 784 + ((lsel >> 1) & 1) * 16);
    const u32 b1B = (u32)((warpn * 128 + lrow + ((lsel >> 1) & 1) * 8) * 80 + (lsel & 1) * 16);

#pragma unroll 1
    for (int ch = 0; ch < 12; ++ch) {
        if (ch < 11) {
            const char* src = (const char*)g_w1p + (ch + 1) * 20480;
            u32 dst = sb + O_W + (u32)((ch + 1) & 1) * 20480;
#pragma unroll
            for (int j = 0; j < 5; ++j) {
                int idx = tid + j * 256;
                cp16(dst + idx * 16, src + idx * 16);
            }
            CP_COMMIT();
        }
        const u32 bb = sb + O_W + (u32)(ch & 1) * 20480 + b1B;
        const u32 kof = (u32)(ch * 64);
#pragma unroll
        for (int ks = 0; ks < 2; ++ks) {
            u32 ah[4];
            ldm4(a1B + kof + ks * 32, ah);
            u32 bf[4][4];
#pragma unroll
            for (int pr = 0; pr < 4; ++pr) ldm4(bb + pr * 1280 + ks * 32, bf[pr]);
#pragma unroll
            for (int pr = 0; pr < 4; ++pr) {
                mma_f16(acc + pr * 8,     ah, bf[pr][0], bf[pr][1]);
                mma_f16(acc + pr * 8 + 4, ah, bf[pr][2], bf[pr][3]);
            }
#pragma unroll
            for (int pr = 0; pr < 4; ++pr) ldm4(bb + (pr + 4) * 1280 + ks * 32, bf[pr]);
#pragma unroll
            for (int pr = 0; pr < 4; ++pr) {
                mma_f16(acc + (pr + 4) * 8,     ah, bf[pr][0], bf[pr][1]);
                mma_f16(acc + (pr + 4) * 8 + 4, ah, bf[pr][2], bf[pr][3]);
            }
        }
        if (ch < 11) {
            CP_WAIT0();
            __syncthreads();
        }
    }

    // issue fc2 chunk-0 staging NOW (buf0 free: its last reads were chunk 10,
    // drained by the chunk-11 entry barrier) -> copy overlaps fc1 epilogue.
    {
        const char* src = (const char*)g_w2p;
        int idx = tid;
        cp16(sb + O_W + idx * 16, src + idx * 16);
        if (tid < 64) {
            idx = 256 + tid;
            cp16(sb + O_W + idx * 16, src + idx * 16);
        }
        CP_COMMIT();
    }
    __syncthreads();   // all warps done reading A1 before A2 overwrites it

    // ---- fc1 epilogue -> A2 fp16 [64][264] ----
    {
        const int r0 = warpm * 16 + g;
#pragma unroll
        for (int nt = 0; nt < 16; ++nt) {
            const int n0 = warpn * 128 + nt * 8 + q * 2;
            float bb0 = SC[SFB1 + n0], bb1 = SC[SFB1 + n0 + 1];
            float v0 = fmaxf(acc[nt * 4 + 0] + bb0, 0.f), v1 = fmaxf(acc[nt * 4 + 1] + bb1, 0.f);
            float v2 = fmaxf(acc[nt * 4 + 2] + bb0, 0.f), v3 = fmaxf(acc[nt * 4 + 3] + bb1, 0.f);
            *(u32*)(smem + O_A2 + r0 * 528 + n0 * 2)       = pack2h(v0, v1);
            *(u32*)(smem + O_A2 + (r0 + 8) * 528 + n0 * 2) = pack2h(v2, v3);
        }
    }
    CP_WAIT0();
    __syncthreads();

    // ---- fc2: 64x64, K=256, fp16 ----
#pragma unroll
    for (int i = 0; i < 16; ++i) acc[i] = 0.f;
    const u32 a2B = sb + O_A2
        + (u32)((warpm * 16 + lrow + (lsel & 1) * 8) * 528 + ((lsel >> 1) & 1) * 16);
    const u32 b2B = (u32)((warpn * 32 + lrow + ((lsel >> 1) & 1) * 8) * 80 + (lsel & 1) * 16);

#pragma unroll 1
    for (int ch = 0; ch < 8; ++ch) {
        if (ch < 7) {
            const char* src = (const char*)g_w2p + (ch + 1) * 5120;
            u32 dst = sb + O_W + (u32)((ch + 1) & 1) * 20480;
            int idx = tid;
            cp16(dst + idx * 16, src + idx * 16);
            if (tid < 64) {
                idx = 256 + tid;
                cp16(dst + idx * 16, src + idx * 16);
            }
            CP_COMMIT();
        }
        const u32 bb = sb + O_W + (u32)(ch & 1) * 20480 + b2B;
        const u32 kof = (u32)(ch * 64);
#pragma unroll
        for (int ks = 0; ks < 2; ++ks) {
            u32 ah[4];
            ldm4(a2B + kof + ks * 32, ah);
            u32 bf[2][4];
#pragma unroll
            for (int pr = 0; pr < 2; ++pr) ldm4(bb + pr * 1280 + ks * 32, bf[pr]);
#pragma unroll
            for (int pr = 0; pr < 2; ++pr) {
                mma_f16(acc + pr * 8,     ah, bf[pr][0], bf[pr][1]);
                mma_f16(acc + pr * 8 + 4, ah, bf[pr][2], bf[pr][3]);
            }
        }
        if (ch < 7) {
            CP_WAIT0();
            __syncthreads();
        }
    }
    __syncthreads();

    // ---- fc2 epilogue -> F2 [64][69] f32 ----
    {
        float* f2 = (float*)(smem + O_F2);
        const int r0 = warpm * 16 + g;
#pragma unroll
        for (int nt = 0; nt < 4; ++nt) {
            const int n0 = warpn * 32 + nt * 8 + q * 2;
            float bb0 = SC[SFB2 + n0], bb1 = SC[SFB2 + n0 + 1];
            f2[r0 * 69 + n0]           = fmaxf(acc[nt * 4 + 0] + bb0, 0.f);
            f2[r0 * 69 + n0 + 1]       = fmaxf(acc[nt * 4 + 1] + bb1, 0.f);
            f2[(r0 + 8) * 69 + n0]     = fmaxf(acc[nt * 4 + 2] + bb0, 0.f);
            f2[(r0 + 8) * 69 + n0 + 1] = fmaxf(acc[nt * 4 + 3] + bb1, 0.f);
        }
    }
    __syncthreads();

    // ---- head (64->12) + log_softmax ----
    if (tid < 64) {
        const float* f2 = (const float*)(smem + O_F2) + tid * 69;
        float l[12];
#pragma unroll
        for (int j = 0; j < 12; ++j) l[j] = SC[SPB + j];
#pragma unroll 8
        for (int k = 0; k < 64; ++k) {
            float v = f2[k];
#pragma unroll
            for (int j = 0; j < 12; ++j) l[j] += v * SC[SPW + j * 64 + k];
        }
        float m = l[0];
#pragma unroll
        for (int j = 1; j < 12; ++j) m = fmaxf(m, l[j]);
        float ssum = 0.f;
#pragma unroll
        for (int j = 0; j < 12; ++j) ssum += __expf(l[j] - m);
        float lse = m + __logf(ssum);
        float* op = out + ((size_t)bx * 64 + tid) * 12;
#pragma unroll
        for (int j = 0; j < 12; ++j) op[j] = l[j] - lse;
    }
}

extern "C" void kernel_launch(void* const* d_in, const int* in_sizes, int n_in,
                              void* d_out, int out_size)
{
    (void)n_in; (void)out_size;
    const float* sig = (const float*)d_in[0];
    const float* w1  = (const float*)d_in[1];
    const float* b1  = (const float*)d_in[2];
    const float* w2  = (const float*)d_in[3];
    const float* b2  = (const float*)d_in[4];
    const float* fw1 = (const float*)d_in[5];
    const float* fb1 = (const float*)d_in[6];
    const float* fw2 = (const float*)d_in[7];
    const float* fb2 = (const float*)d_in[8];
    const float* pw  = (const float*)d_in[9];
    const float* pb  = (const float*)d_in[10];
    float* out = (float*)d_out;

    const int B = in_sizes[0] / 150;
    prep_kernel<<<480, 256>>>(fw1, fw2);
    cudaFuncSetAttribute(convnet_mma_kernel, cudaFuncAttributeMaxDynamicSharedMemorySize, SMB);
    convnet_mma_kernel<<<B / 64, NT, SMB>>>(sig, w1, b1, w2, b2, fb1, fb2, pw, pb, out);
}